// round 7
// baseline (speedup 1.0000x reference)
#include <cuda_runtime.h>
#include <math.h>

#define B_  256
#define L_  16
#define H_  512
#define G4  2048      // 4*H
#define D2  1024      // 2*H
#define G5  5120      // 5*D2
#define NN  31        // 16 leaves + 15 internal nodes

// ---------------- scratch (static device globals; no allocation) ----------------
__device__ float g_xg[2][B_][L_][G4];      // input projections, fwd/bwd (bwd in reversed time order)
__device__ float g_gbuf[2][B_][G4];        // per-step gate pre-activations
__device__ float g_hst[2][B_][H_];         // running LSTM h
__device__ float g_cst[2][B_][H_];         // running LSTM c
__device__ float g_nodeH[NN][B_][D2];      // node h (node-major so GEMM rows are contiguous)
__device__ float g_nodeC[NN][B_][D2];      // node c
__device__ float g_PL[NN][B_][G5];         // cached h @ Wl^T
__device__ float g_PR[NN][B_][G5];         // cached h @ Wr^T
__device__ float g_logit[B_][L_];          // cached pair logits (current sequence order)
__device__ int   g_seq[B_][L_];            // current sequence -> node id
__device__ int   g_selpos[B_];             // selected pair position this iteration
__device__ int   g_rowmap[B_ * L_];        // row gather map for backward-LSTM input reversal

__device__ __forceinline__ float sigm(float x) { return 1.0f / (1.0f + expf(-x)); }

// ---------------- packed fp32x2 helpers (sm_103a 2x-rate fp32 path) ----------------
__device__ __forceinline__ unsigned long long pack2(float lo, float hi) {
    unsigned long long r;
    asm("mov.b64 %0, {%1, %2};" : "=l"(r)
        : "r"(__float_as_uint(lo)), "r"(__float_as_uint(hi)));
    return r;
}
__device__ __forceinline__ unsigned long long fma2(unsigned long long a,
                                                   unsigned long long b,
                                                   unsigned long long c) {
    unsigned long long d;
    asm("fma.rn.f32x2 %0, %1, %2, %3;" : "=l"(d) : "l"(a), "l"(b), "l"(c));
    return d;
}
__device__ __forceinline__ float2 unpack2(unsigned long long v) {
    unsigned int lo, hi;
    asm("mov.b64 {%0, %1}, %2;" : "=r"(lo), "=r"(hi) : "l"(v));
    return make_float2(__uint_as_float(lo), __uint_as_float(hi));
}

// ---------------- init: zero LSTM state, build reversal map, seq identity ----------------
__global__ void k_init(const int* __restrict__ len) {
    int idx = blockIdx.x * blockDim.x + threadIdx.x;
    if (idx < 2 * B_ * H_) {
        ((float*)g_hst)[idx] = 0.0f;
        ((float*)g_cst)[idx] = 0.0f;
    }
    if (idx < B_ * L_) {
        int b = idx / L_, t = idx % L_;
        int ln = len[b];
        g_rowmap[idx] = b * L_ + ((t < ln) ? (ln - 1 - t) : t);
        g_seq[b][t] = t;
    }
}

// ---------------- generic fp32 NT GEMM: C[m][n] = sum_k A[m][k] * W[n][k] (+bias +add) ---------
// Inner product accumulated with fma.rn.f32x2 (bit-identical to scalar fmaf per lane).
// Optional split output: columns >= nsplit use (W1, C1) with col-nsplit — lets one launch
// compute PL (h@Wl^T) and PR (h@Wr^T) where Wl/Wr are column slices of w_comp (ldw=2048).
template<int BM, int BN, int BK, int TM, int TN, int NT>
__global__ void __launch_bounds__(NT) gemm_nt(
    const float* __restrict__ A, int lda, const int* __restrict__ rowmap,
    const float* __restrict__ W0, const float* __restrict__ W1, int ldw, int nsplit,
    const float* __restrict__ bias,
    const float* __restrict__ add, long long ldadd,
    float* __restrict__ C0, float* __restrict__ C1, int ldc,
    int K)
{
    __shared__ float As[BK][BM];
    __shared__ float Ws[BK][BN];

    const int tid = threadIdx.x;
    const int n0 = blockIdx.x * BN;
    const int m0 = blockIdx.y * BM;

    const float* W = W0;
    float* C = C0;
    int nc0 = n0;
    if (nsplit > 0 && n0 >= nsplit) { W = W1; C = C1; nc0 = n0 - nsplit; }

    constexpr int TN2 = TN / 2;
    unsigned long long acc2[TM][TN2];
#pragma unroll
    for (int i = 0; i < TM; i++)
#pragma unroll
        for (int j = 0; j < TN2; j++) acc2[i][j] = 0ull;   // two packed fp32 zeros

    constexpr int KQ = BK / 4;                    // float4 slots along K
    constexpr int ALOAD = (BM * BK) / (4 * NT);
    constexpr int WLOAD = (BN * BK) / (4 * NT);

    const int tx = tid % (BN / TN);
    const int ty = tid / (BN / TN);

    for (int k0 = 0; k0 < K; k0 += BK) {
#pragma unroll
        for (int i = 0; i < ALOAD; i++) {
            int e = tid + i * NT;
            int r = e / KQ;
            int kq = (e % KQ) * 4;
            int gr = m0 + r;
            int sr = rowmap ? rowmap[gr] : gr;
            float4 v = *reinterpret_cast<const float4*>(A + (size_t)sr * lda + k0 + kq);
            As[kq + 0][r] = v.x; As[kq + 1][r] = v.y; As[kq + 2][r] = v.z; As[kq + 3][r] = v.w;
        }
#pragma unroll
        for (int i = 0; i < WLOAD; i++) {
            int e = tid + i * NT;
            int r = e / KQ;
            int kq = (e % KQ) * 4;
            float4 v = *reinterpret_cast<const float4*>(W + (size_t)(nc0 + r) * ldw + k0 + kq);
            Ws[kq + 0][r] = v.x; Ws[kq + 1][r] = v.y; Ws[kq + 2][r] = v.z; Ws[kq + 3][r] = v.w;
        }
        __syncthreads();

#pragma unroll
        for (int kk = 0; kk < BK; kk++) {
            float ra[TM];
            unsigned long long rb2[TN2];
#pragma unroll
            for (int i = 0; i < TM; i += 4)
                *reinterpret_cast<float4*>(&ra[i]) =
                    *reinterpret_cast<const float4*>(&As[kk][ty * TM + i]);
#pragma unroll
            for (int j = 0; j < TN2; j++)
                rb2[j] = *reinterpret_cast<const unsigned long long*>(&Ws[kk][tx * TN + j * 2]);
#pragma unroll
            for (int i = 0; i < TM; i++) {
                unsigned long long aa = pack2(ra[i], ra[i]);
#pragma unroll
                for (int j = 0; j < TN2; j++)
                    acc2[i][j] = fma2(aa, rb2[j], acc2[i][j]);
            }
        }
        __syncthreads();
    }

#pragma unroll
    for (int i = 0; i < TM; i++) {
        size_t row = (size_t)(m0 + ty * TM + i);
#pragma unroll
        for (int j = 0; j < TN2; j++) {
            float2 v2 = unpack2(acc2[i][j]);
            int col = nc0 + tx * TN + j * 2;
            float v0 = v2.x, v1 = v2.y;
            if (bias) { v0 += bias[col]; v1 += bias[col + 1]; }
            if (add)  { v0 += add[row * (size_t)ldadd + col];
                        v1 += add[row * (size_t)ldadd + col + 1]; }
            C[row * (size_t)ldc + col]     = v0;
            C[row * (size_t)ldc + col + 1] = v1;
        }
    }
}

// ---------------- recurrent-step GEMM, both directions in one launch (blockIdx.z = dir) -------
// gbuf[z] = hst[z] @ whh[z]^T + xg[z][:, t, :]   for z in {0,1}
// Same tiling/accumulation order as gemm_nt<64,64,16,4,4,256> -> bit-identical numerics.
__global__ void __launch_bounds__(256) gemm_rec(
    const float* __restrict__ whhf, const float* __restrict__ whhb, int t)
{
    constexpr int BM = 64, BN = 64, BK = 16, TM = 4, TN = 4, NT = 256;
    __shared__ float As[BK][BM];
    __shared__ float Ws[BK][BN];

    const int tid = threadIdx.x;
    const int n0 = blockIdx.x * BN;
    const int m0 = blockIdx.y * BM;
    const int z  = blockIdx.z;

    const float* A   = &g_hst[z][0][0];                 // [B_][H_]
    const float* W   = z ? whhb : whhf;                 // [G4][H_]
    const float* add = &g_xg[z][0][t][0];               // row stride L_*G4
    float*       C   = &g_gbuf[z][0][0];                // [B_][G4]

    constexpr int TN2 = TN / 2;
    unsigned long long acc2[TM][TN2];
#pragma unroll
    for (int i = 0; i < TM; i++)
#pragma unroll
        for (int j = 0; j < TN2; j++) acc2[i][j] = 0ull;

    constexpr int KQ = BK / 4;          // 4
    const int tx = tid % (BN / TN);
    const int ty = tid / (BN / TN);

    for (int k0 = 0; k0 < H_; k0 += BK) {
        {   // ALOAD = 1
            int r = tid / KQ;
            int kq = (tid % KQ) * 4;
            float4 v = *reinterpret_cast<const float4*>(A + (size_t)(m0 + r) * H_ + k0 + kq);
            As[kq + 0][r] = v.x; As[kq + 1][r] = v.y; As[kq + 2][r] = v.z; As[kq + 3][r] = v.w;
        }
        {   // WLOAD = 1
            int r = tid / KQ;
            int kq = (tid % KQ) * 4;
            float4 v = *reinterpret_cast<const float4*>(W + (size_t)(n0 + r) * H_ + k0 + kq);
            Ws[kq + 0][r] = v.x; Ws[kq + 1][r] = v.y; Ws[kq + 2][r] = v.z; Ws[kq + 3][r] = v.w;
        }
        __syncthreads();

#pragma unroll
        for (int kk = 0; kk < BK; kk++) {
            float ra[TM];
            unsigned long long rb2[TN2];
            *reinterpret_cast<float4*>(&ra[0]) =
                *reinterpret_cast<const float4*>(&As[kk][ty * TM]);
#pragma unroll
            for (int j = 0; j < TN2; j++)
                rb2[j] = *reinterpret_cast<const unsigned long long*>(&Ws[kk][tx * TN + j * 2]);
#pragma unroll
            for (int i = 0; i < TM; i++) {
                unsigned long long aa = pack2(ra[i], ra[i]);
#pragma unroll
                for (int j = 0; j < TN2; j++)
                    acc2[i][j] = fma2(aa, rb2[j], acc2[i][j]);
            }
        }
        __syncthreads();
    }

#pragma unroll
    for (int i = 0; i < TM; i++) {
        size_t row = (size_t)(m0 + ty * TM + i);
#pragma unroll
        for (int j = 0; j < TN2; j++) {
            float2 v2 = unpack2(acc2[i][j]);
            int col = n0 + tx * TN + j * 2;
            C[row * G4 + col]     = v2.x + add[row * (size_t)(L_ * G4) + col];
            C[row * G4 + col + 1] = v2.y + add[row * (size_t)(L_ * G4) + col + 1];
        }
    }
}

// ---------------- LSTM gate elementwise (both directions), writes leaves ----------------
__global__ void k_gates(int t, const int* __restrict__ len) {
    int idx = blockIdx.x * blockDim.x + threadIdx.x;
    if (idx >= 2 * B_ * H_) return;
    int d = idx >> 17;                    // B_*H_ = 131072 = 1<<17
    int r = idx & ((1 << 17) - 1);
    int b = r >> 9;                       // H_ = 512 = 1<<9
    int j = r & (H_ - 1);

    const float* gb = &g_gbuf[d][b][0];
    float gi = gb[j];
    float gf = gb[H_ + j];
    float gu = gb[2 * H_ + j];
    float go = gb[3 * H_ + j];
    float cp = g_cst[d][b][j];
    float cn = sigm(gf) * cp + sigm(gi) * tanhf(gu);
    float hn = sigm(go) * tanhf(cn);
    g_cst[d][b][j] = cn;
    g_hst[d][b][j] = hn;

    int ln = len[b];
    int pos = (d == 0) ? t : ((t < ln) ? (ln - 1 - t) : t);
    g_nodeH[pos][b][d * H_ + j] = hn;
    g_nodeC[pos][b][d * H_ + j] = cn;
}

// ---------------- pair logit from cached projections (block-collective, 256 threads) --------
__device__ float pair_logit(int b, int nl, int nr,
                            const float* __restrict__ bcomp, const float* __restrict__ wq)
{
    const float* pl = &g_PL[nl][b][0];
    const float* pr = &g_PR[nr][b][0];
    const float* cl = &g_nodeC[nl][b][0];
    const float* cr = &g_nodeC[nr][b][0];
    float part = 0.0f;
    for (int d = threadIdx.x; d < D2; d += blockDim.x) {
        float vi  = pl[d]          + pr[d]          + bcomp[d];
        float vfl = pl[D2 + d]     + pr[D2 + d]     + bcomp[D2 + d];
        float vfr = pl[2 * D2 + d] + pr[2 * D2 + d] + bcomp[2 * D2 + d];
        float vu  = pl[3 * D2 + d] + pr[3 * D2 + d] + bcomp[3 * D2 + d];
        float vo  = pl[4 * D2 + d] + pr[4 * D2 + d] + bcomp[4 * D2 + d];
        float cn = cl[d] * sigm(vfl + 1.0f) + cr[d] * sigm(vfr + 1.0f) + tanhf(vu) * sigm(vi);
        float hn = sigm(vo) * tanhf(cn);
        part += hn * wq[d];
    }
    __shared__ float red[8];
    for (int off = 16; off; off >>= 1) part += __shfl_down_sync(0xffffffffu, part, off);
    if ((threadIdx.x & 31) == 0) red[threadIdx.x >> 5] = part;
    __syncthreads();
    float s = 0.0f;
    if (threadIdx.x == 0)
        for (int w = 0; w < 8; w++) s += red[w];
    return s;
}

__global__ void k_pairinit(const int* __restrict__ len,
                           const float* __restrict__ bcomp, const float* __restrict__ wq) {
    int p = blockIdx.x, b = blockIdx.y;
    int ln = len[b];
    if (p > ln - 2) return;   // block-uniform
    float lg = pair_logit(b, g_seq[b][p], g_seq[b][p + 1], bcomp, wq);
    if (threadIdx.x == 0) g_logit[b][p] = lg;
}

// ---------------- per-iteration: argmax select + compose the chosen pair ----------------
__global__ void k_compose(int it, const int* __restrict__ len, const float* __restrict__ bcomp) {
    int b = blockIdx.x;
    int ln = len[b];
    if (ln - 1 <= it) {
        // inactive: zero the would-be new node so projection GEMM stays well-defined
        for (int d = threadIdx.x; d < D2; d += blockDim.x) g_nodeH[16 + it][b][d] = 0.0f;
        return;
    }
    __shared__ int sh[3];
    if (threadIdx.x == 0) {
        int vp = ln - 1 - it;               // remaining valid pairs
        int k = 0; float best = g_logit[b][0];
        for (int p = 1; p < vp; p++) {
            float v = g_logit[b][p];
            if (v > best) { best = v; k = p; }   // strict > = first-max tiebreak (matches argmax)
        }
        sh[0] = k; sh[1] = g_seq[b][k]; sh[2] = g_seq[b][k + 1];
    }
    __syncthreads();
    int k = sh[0], nl = sh[1], nr = sh[2];

    const float* pl = &g_PL[nl][b][0];
    const float* pr = &g_PR[nr][b][0];
    const float* cl = &g_nodeC[nl][b][0];
    const float* cr = &g_nodeC[nr][b][0];
    for (int d = threadIdx.x; d < D2; d += blockDim.x) {
        float vi  = pl[d]          + pr[d]          + bcomp[d];
        float vfl = pl[D2 + d]     + pr[D2 + d]     + bcomp[D2 + d];
        float vfr = pl[2 * D2 + d] + pr[2 * D2 + d] + bcomp[2 * D2 + d];
        float vu  = pl[3 * D2 + d] + pr[3 * D2 + d] + bcomp[3 * D2 + d];
        float vo  = pl[4 * D2 + d] + pr[4 * D2 + d] + bcomp[4 * D2 + d];
        float cn = cl[d] * sigm(vfl + 1.0f) + cr[d] * sigm(vfr + 1.0f) + tanhf(vu) * sigm(vi);
        float hn = sigm(vo) * tanhf(cn);
        g_nodeH[16 + it][b][d] = hn;
        g_nodeC[16 + it][b][d] = cn;
    }
    if (threadIdx.x == 0) {
        g_selpos[b] = k;
        for (int p = k + 1; p <= ln - 2 - it; p++) g_seq[b][p] = g_seq[b][p + 1];
        g_seq[b][k] = 16 + it;
        for (int p = k + 1; p <= ln - 3 - it; p++) g_logit[b][p] = g_logit[b][p + 1];
    }
}

// refresh the <=2 logits adjacent to the new node (after its projection GEMM)
__global__ void k_update(int it, const int* __restrict__ len,
                         const float* __restrict__ bcomp, const float* __restrict__ wq) {
    int b = blockIdx.y, q = blockIdx.x;       // q=0 -> pair k-1, q=1 -> pair k
    int ln = len[b];
    if (ln - 2 <= it) return;                 // no pairs remain for this batch
    int k = g_selpos[b];
    int p = k - 1 + q;
    if (p < 0) return;
    int np = ln - 2 - it;
    if (p >= np) return;
    float lg = pair_logit(b, g_seq[b][p], g_seq[b][p + 1], bcomp, wq);
    if (threadIdx.x == 0) g_logit[b][p] = lg;
}

__global__ void k_output(const int* __restrict__ len, float* __restrict__ out) {
    int idx = blockIdx.x * blockDim.x + threadIdx.x;
    if (idx >= B_ * D2) return;
    int b = idx >> 10;
    int d = idx & (D2 - 1);
    out[idx] = g_nodeH[14 + len[b]][b][d];    // root node id = 16 + (len-2)
}

// ---------------- orchestration ----------------
extern "C" void kernel_launch(void* const* d_in, const int* in_sizes, int n_in,
                              void* d_out, int out_size) {
    const float* x     = (const float*)d_in[0];
    const int*   len   = (const int*)  d_in[1];
    const float* wihf  = (const float*)d_in[2];
    const float* whhf  = (const float*)d_in[3];
    const float* bf    = (const float*)d_in[4];
    const float* wihb  = (const float*)d_in[5];
    const float* whhb  = (const float*)d_in[6];
    const float* bb    = (const float*)d_in[7];
    const float* wcomp = (const float*)d_in[8];
    const float* bcomp = (const float*)d_in[9];
    const float* wq    = (const float*)d_in[10];
    float* out = (float*)d_out;

    float *p_xg, *p_nH, *p_PL, *p_PR;
    int* p_rm;
    cudaGetSymbolAddress((void**)&p_xg,   g_xg);
    cudaGetSymbolAddress((void**)&p_nH,   g_nodeH);
    cudaGetSymbolAddress((void**)&p_PL,   g_PL);
    cudaGetSymbolAddress((void**)&p_PR,   g_PR);
    cudaGetSymbolAddress((void**)&p_rm,   g_rowmap);

    k_init<<<(2 * B_ * H_ + 255) / 256, 256>>>(len);

    // input projections: xg_f = x @ w_ih_f^T + b_f ; xg_b = gather(x) @ w_ih_b^T + b_b
    gemm_nt<128,128,16,8,8,256><<<dim3(G4/128, (B_*L_)/128), 256>>>(
        x, H_, nullptr, wihf, nullptr, H_, 0, bf, nullptr, 0,
        p_xg, nullptr, G4, H_);
    gemm_nt<128,128,16,8,8,256><<<dim3(G4/128, (B_*L_)/128), 256>>>(
        x, H_, p_rm, wihb, nullptr, H_, 0, bb, nullptr, 0,
        p_xg + (size_t)B_ * L_ * G4, nullptr, G4, H_);

    // 16 sequential LSTM steps: fused fwd+bwd recurrent GEMM, then gates
    for (int t = 0; t < L_; t++) {
        gemm_rec<<<dim3(G4/64, B_/64, 2), 256>>>(whhf, whhb, t);
        k_gates<<<(2 * B_ * H_ + 255) / 256, 256>>>(t, len);
    }

    // leaf projections: PL/PR for all 16 leaves in one split GEMM (N = 2*5120)
    gemm_nt<128,128,16,8,8,256><<<dim3((2*G5)/128, (16*B_)/128), 256>>>(
        p_nH, D2, nullptr, wcomp, wcomp + D2, 2 * D2, G5,
        nullptr, nullptr, 0, p_PL, p_PR, G5, D2);

    // initial pair logits
    k_pairinit<<<dim3(L_ - 1, B_), 256>>>(len, bcomp, wq);

    // 15 composition iterations
    for (int it = 0; it < L_ - 1; it++) {
        k_compose<<<B_, 256>>>(it, len, bcomp);
        if (it < L_ - 2) {
            gemm_nt<64,128,16,4,8,256><<<dim3((2*G5)/128, B_/64), 256>>>(
                p_nH + (size_t)(16 + it) * B_ * D2, D2, nullptr,
                wcomp, wcomp + D2, 2 * D2, G5,
                nullptr, nullptr, 0,
                p_PL + (size_t)(16 + it) * B_ * G5,
                p_PR + (size_t)(16 + it) * B_ * G5, G5, D2);
            k_update<<<dim3(2, B_), 256>>>(it, len, bcomp, wq);
        }
    }

    k_output<<<(B_ * D2 + 255) / 256, 256>>>(len, out);
}

// round 9
// speedup vs baseline: 1.0049x; 1.0049x over previous
#include <cuda_runtime.h>
#include <math.h>

#define B_  256
#define L_  16
#define H_  512
#define G4  2048      // 4*H
#define D2  1024      // 2*H
#define G5  5120      // 5*D2
#define NN  31        // 16 leaves + 15 internal nodes

// ---------------- scratch (static device globals; no allocation) ----------------
__device__ float g_xg[2][B_][L_][G4];      // input projections, fwd/bwd (bwd in reversed time order)
__device__ float g_gbuf[2][B_][G4];        // per-step gate pre-activations
__device__ float g_hst[2][B_][H_];         // running LSTM h
__device__ float g_cst[2][B_][H_];         // running LSTM c
__device__ float g_nodeH[NN][B_][D2];      // node h (node-major so GEMM rows are contiguous)
__device__ float g_nodeC[NN][B_][D2];      // node c
__device__ float g_PL[NN][B_][G5];         // cached h @ Wl^T
__device__ float g_PR[NN][B_][G5];         // cached h @ Wr^T
__device__ float g_logit[B_][L_];          // cached pair logits (current sequence order)
__device__ int   g_seq[B_][L_];            // current sequence -> node id
__device__ int   g_selpos[B_];             // selected pair position this iteration
__device__ int   g_rowmap[B_ * L_];        // row gather map for backward-LSTM input reversal

__device__ __forceinline__ float sigm(float x) { return 1.0f / (1.0f + expf(-x)); }

// ---------------- packed fp32x2 helpers (sm_103a 2x-rate fp32 path) ----------------
__device__ __forceinline__ unsigned long long pack2(float lo, float hi) {
    unsigned long long r;
    asm("mov.b64 %0, {%1, %2};" : "=l"(r)
        : "r"(__float_as_uint(lo)), "r"(__float_as_uint(hi)));
    return r;
}
__device__ __forceinline__ unsigned long long fma2(unsigned long long a,
                                                   unsigned long long b,
                                                   unsigned long long c) {
    unsigned long long d;
    asm("fma.rn.f32x2 %0, %1, %2, %3;" : "=l"(d) : "l"(a), "l"(b), "l"(c));
    return d;
}
__device__ __forceinline__ float2 unpack2(unsigned long long v) {
    unsigned int lo, hi;
    asm("mov.b64 {%0, %1}, %2;" : "=r"(lo), "=r"(hi) : "l"(v));
    return make_float2(__uint_as_float(lo), __uint_as_float(hi));
}

// ---------------- init: zero LSTM state, build reversal map, seq identity ----------------
__global__ void k_init(const int* __restrict__ len) {
    int idx = blockIdx.x * blockDim.x + threadIdx.x;
    if (idx < 2 * B_ * H_) {
        ((float*)g_hst)[idx] = 0.0f;
        ((float*)g_cst)[idx] = 0.0f;
    }
    if (idx < B_ * L_) {
        int b = idx / L_, t = idx % L_;
        int ln = len[b];
        g_rowmap[idx] = b * L_ + ((t < ln) ? (ln - 1 - t) : t);
        g_seq[b][t] = t;
    }
}

// ---------------- generic fp32 NT GEMM, double-buffered smem pipeline --------------------
// C[m][n] = sum_k A[m][k] * W[n][k] (+bias +add); fma.rn.f32x2 accumulation (bit-identical
// per lane to scalar fmaf, same kk order). Global loads for tile kt+1 are issued before the
// compute on tile kt and stored to the alternate smem buffer after compute -> LDG latency
// is hidden behind the FFMA2 stream; one __syncthreads per K-tile.
template<int BM, int BN, int BK, int TM, int TN, int NT>
__global__ void __launch_bounds__(NT) gemm_nt(
    const float* __restrict__ A, int lda, const int* __restrict__ rowmap,
    const float* __restrict__ W0, const float* __restrict__ W1, int ldw, int nsplit,
    const float* __restrict__ bias,
    const float* __restrict__ add, long long ldadd,
    float* __restrict__ C0, float* __restrict__ C1, int ldc,
    int K)
{
    __shared__ float As[2][BK][BM];
    __shared__ float Ws[2][BK][BN];

    const int tid = threadIdx.x;
    const int n0 = blockIdx.x * BN;
    const int m0 = blockIdx.y * BM;

    const float* W = W0;
    float* C = C0;
    int nc0 = n0;
    if (nsplit > 0 && n0 >= nsplit) { W = W1; C = C1; nc0 = n0 - nsplit; }

    constexpr int TN2 = TN / 2;
    unsigned long long acc2[TM][TN2];
#pragma unroll
    for (int i = 0; i < TM; i++)
#pragma unroll
        for (int j = 0; j < TN2; j++) acc2[i][j] = 0ull;

    constexpr int KQ = BK / 4;                    // float4 slots along K
    constexpr int ALOAD = (BM * BK) / (4 * NT);
    constexpr int WLOAD = (BN * BK) / (4 * NT);

    const int tx = tid % (BN / TN);
    const int ty = tid / (BN / TN);

    float4 av[ALOAD], wv[WLOAD];

    // prologue: load tile 0
#pragma unroll
    for (int i = 0; i < ALOAD; i++) {
        int e = tid + i * NT;
        int gr = m0 + e / KQ;
        int sr = rowmap ? rowmap[gr] : gr;
        av[i] = *reinterpret_cast<const float4*>(A + (size_t)sr * lda + (e % KQ) * 4);
    }
#pragma unroll
    for (int i = 0; i < WLOAD; i++) {
        int e = tid + i * NT;
        wv[i] = *reinterpret_cast<const float4*>(W + (size_t)(nc0 + e / KQ) * ldw + (e % KQ) * 4);
    }
#pragma unroll
    for (int i = 0; i < ALOAD; i++) {
        int e = tid + i * NT;
        int r = e / KQ, kq = (e % KQ) * 4;
        As[0][kq + 0][r] = av[i].x; As[0][kq + 1][r] = av[i].y;
        As[0][kq + 2][r] = av[i].z; As[0][kq + 3][r] = av[i].w;
    }
#pragma unroll
    for (int i = 0; i < WLOAD; i++) {
        int e = tid + i * NT;
        int r = e / KQ, kq = (e % KQ) * 4;
        Ws[0][kq + 0][r] = wv[i].x; Ws[0][kq + 1][r] = wv[i].y;
        Ws[0][kq + 2][r] = wv[i].z; Ws[0][kq + 3][r] = wv[i].w;
    }
    __syncthreads();

    const int KT = K / BK;
    for (int kt = 0; kt < KT; kt++) {
        const int cur = kt & 1;
        // issue next tile's global loads (latency overlapped with compute below)
        if (kt + 1 < KT) {
            int k0n = (kt + 1) * BK;
#pragma unroll
            for (int i = 0; i < ALOAD; i++) {
                int e = tid + i * NT;
                int gr = m0 + e / KQ;
                int sr = rowmap ? rowmap[gr] : gr;
                av[i] = *reinterpret_cast<const float4*>(A + (size_t)sr * lda + k0n + (e % KQ) * 4);
            }
#pragma unroll
            for (int i = 0; i < WLOAD; i++) {
                int e = tid + i * NT;
                wv[i] = *reinterpret_cast<const float4*>(W + (size_t)(nc0 + e / KQ) * ldw + k0n + (e % KQ) * 4);
            }
        }

#pragma unroll
        for (int kk = 0; kk < BK; kk++) {
            float ra[TM];
            unsigned long long rb2[TN2];
#pragma unroll
            for (int i = 0; i < TM; i += 4)
                *reinterpret_cast<float4*>(&ra[i]) =
                    *reinterpret_cast<const float4*>(&As[cur][kk][ty * TM + i]);
#pragma unroll
            for (int j = 0; j < TN2; j++)
                rb2[j] = *reinterpret_cast<const unsigned long long*>(&Ws[cur][kk][tx * TN + j * 2]);
#pragma unroll
            for (int i = 0; i < TM; i++) {
                unsigned long long aa = pack2(ra[i], ra[i]);
#pragma unroll
                for (int j = 0; j < TN2; j++)
                    acc2[i][j] = fma2(aa, rb2[j], acc2[i][j]);
            }
        }

        if (kt + 1 < KT) {
            const int nxt = (kt + 1) & 1;
#pragma unroll
            for (int i = 0; i < ALOAD; i++) {
                int e = tid + i * NT;
                int r = e / KQ, kq = (e % KQ) * 4;
                As[nxt][kq + 0][r] = av[i].x; As[nxt][kq + 1][r] = av[i].y;
                As[nxt][kq + 2][r] = av[i].z; As[nxt][kq + 3][r] = av[i].w;
            }
#pragma unroll
            for (int i = 0; i < WLOAD; i++) {
                int e = tid + i * NT;
                int r = e / KQ, kq = (e % KQ) * 4;
                Ws[nxt][kq + 0][r] = wv[i].x; Ws[nxt][kq + 1][r] = wv[i].y;
                Ws[nxt][kq + 2][r] = wv[i].z; Ws[nxt][kq + 3][r] = wv[i].w;
            }
        }
        __syncthreads();
    }

#pragma unroll
    for (int i = 0; i < TM; i++) {
        size_t row = (size_t)(m0 + ty * TM + i);
#pragma unroll
        for (int j = 0; j < TN2; j++) {
            float2 v2 = unpack2(acc2[i][j]);
            int col = nc0 + tx * TN + j * 2;
            float v0 = v2.x, v1 = v2.y;
            if (bias) { v0 += bias[col]; v1 += bias[col + 1]; }
            if (add)  { v0 += add[row * (size_t)ldadd + col];
                        v1 += add[row * (size_t)ldadd + col + 1]; }
            C[row * (size_t)ldc + col]     = v0;
            C[row * (size_t)ldc + col + 1] = v1;
        }
    }
}

// ---------------- recurrent-step GEMM, both directions, double-buffered ----------------
// gbuf[z] = hst[z] @ whh[z]^T + xg[z][:, t, :]  (blockIdx.z = direction)
__global__ void __launch_bounds__(256) gemm_rec(
    const float* __restrict__ whhf, const float* __restrict__ whhb, int t)
{
    constexpr int BM = 64, BN = 64, BK = 16, TM = 4, TN = 4, NT = 256;
    __shared__ float As[2][BK][BM];
    __shared__ float Ws[2][BK][BN];

    const int tid = threadIdx.x;
    const int n0 = blockIdx.x * BN;
    const int m0 = blockIdx.y * BM;
    const int z  = blockIdx.z;

    const float* A   = &g_hst[z][0][0];
    const float* W   = z ? whhb : whhf;
    const float* add = &g_xg[z][0][t][0];
    float*       C   = &g_gbuf[z][0][0];

    constexpr int TN2 = TN / 2;
    unsigned long long acc2[TM][TN2];
#pragma unroll
    for (int i = 0; i < TM; i++)
#pragma unroll
        for (int j = 0; j < TN2; j++) acc2[i][j] = 0ull;

    constexpr int KQ = BK / 4;
    const int tx = tid % (BN / TN);
    const int ty = tid / (BN / TN);
    const int lr = tid / KQ;
    const int lk = (tid % KQ) * 4;

    float4 av, wv;
    av = *reinterpret_cast<const float4*>(A + (size_t)(m0 + lr) * H_ + lk);
    wv = *reinterpret_cast<const float4*>(W + (size_t)(n0 + lr) * H_ + lk);
    As[0][lk + 0][lr] = av.x; As[0][lk + 1][lr] = av.y; As[0][lk + 2][lr] = av.z; As[0][lk + 3][lr] = av.w;
    Ws[0][lk + 0][lr] = wv.x; Ws[0][lk + 1][lr] = wv.y; Ws[0][lk + 2][lr] = wv.z; Ws[0][lk + 3][lr] = wv.w;
    __syncthreads();

    const int KT = H_ / BK;
    for (int kt = 0; kt < KT; kt++) {
        const int cur = kt & 1;
        if (kt + 1 < KT) {
            int k0n = (kt + 1) * BK;
            av = *reinterpret_cast<const float4*>(A + (size_t)(m0 + lr) * H_ + k0n + lk);
            wv = *reinterpret_cast<const float4*>(W + (size_t)(n0 + lr) * H_ + k0n + lk);
        }

#pragma unroll
        for (int kk = 0; kk < BK; kk++) {
            float ra[TM];
            unsigned long long rb2[TN2];
            *reinterpret_cast<float4*>(&ra[0]) =
                *reinterpret_cast<const float4*>(&As[cur][kk][ty * TM]);
#pragma unroll
            for (int j = 0; j < TN2; j++)
                rb2[j] = *reinterpret_cast<const unsigned long long*>(&Ws[cur][kk][tx * TN + j * 2]);
#pragma unroll
            for (int i = 0; i < TM; i++) {
                unsigned long long aa = pack2(ra[i], ra[i]);
#pragma unroll
                for (int j = 0; j < TN2; j++)
                    acc2[i][j] = fma2(aa, rb2[j], acc2[i][j]);
            }
        }

        if (kt + 1 < KT) {
            const int nxt = (kt + 1) & 1;
            As[nxt][lk + 0][lr] = av.x; As[nxt][lk + 1][lr] = av.y;
            As[nxt][lk + 2][lr] = av.z; As[nxt][lk + 3][lr] = av.w;
            Ws[nxt][lk + 0][lr] = wv.x; Ws[nxt][lk + 1][lr] = wv.y;
            Ws[nxt][lk + 2][lr] = wv.z; Ws[nxt][lk + 3][lr] = wv.w;
        }
        __syncthreads();
    }

#pragma unroll
    for (int i = 0; i < TM; i++) {
        size_t row = (size_t)(m0 + ty * TM + i);
#pragma unroll
        for (int j = 0; j < TN2; j++) {
            float2 v2 = unpack2(acc2[i][j]);
            int col = n0 + tx * TN + j * 2;
            C[row * G4 + col]     = v2.x + add[row * (size_t)(L_ * G4) + col];
            C[row * G4 + col + 1] = v2.y + add[row * (size_t)(L_ * G4) + col + 1];
        }
    }
}

// ---------------- LSTM gate elementwise (both directions), writes leaves ----------------
__global__ void k_gates(int t, const int* __restrict__ len) {
    int idx = blockIdx.x * blockDim.x + threadIdx.x;
    if (idx >= 2 * B_ * H_) return;
    int d = idx >> 17;                    // B_*H_ = 131072 = 1<<17
    int r = idx & ((1 << 17) - 1);
    int b = r >> 9;                       // H_ = 512 = 1<<9
    int j = r & (H_ - 1);

    const float* gb = &g_gbuf[d][b][0];
    float gi = gb[j];
    float gf = gb[H_ + j];
    float gu = gb[2 * H_ + j];
    float go = gb[3 * H_ + j];
    float cp = g_cst[d][b][j];
    float cn = sigm(gf) * cp + sigm(gi) * tanhf(gu);
    float hn = sigm(go) * tanhf(cn);
    g_cst[d][b][j] = cn;
    g_hst[d][b][j] = hn;

    int ln = len[b];
    int pos = (d == 0) ? t : ((t < ln) ? (ln - 1 - t) : t);
    g_nodeH[pos][b][d * H_ + j] = hn;
    g_nodeC[pos][b][d * H_ + j] = cn;
}

// ---------------- pair logit from cached projections (block-collective, 256 threads) --------
__device__ float pair_logit(int b, int nl, int nr,
                            const float* __restrict__ bcomp, const float* __restrict__ wq)
{
    const float* pl = &g_PL[nl][b][0];
    const float* pr = &g_PR[nr][b][0];
    const float* cl = &g_nodeC[nl][b][0];
    const float* cr = &g_nodeC[nr][b][0];
    float part = 0.0f;
    for (int d = threadIdx.x; d < D2; d += blockDim.x) {
        float vi  = pl[d]          + pr[d]          + bcomp[d];
        float vfl = pl[D2 + d]     + pr[D2 + d]     + bcomp[D2 + d];
        float vfr = pl[2 * D2 + d] + pr[2 * D2 + d] + bcomp[2 * D2 + d];
        float vu  = pl[3 * D2 + d] + pr[3 * D2 + d] + bcomp[3 * D2 + d];
        float vo  = pl[4 * D2 + d] + pr[4 * D2 + d] + bcomp[4 * D2 + d];
        float cn = cl[d] * sigm(vfl + 1.0f) + cr[d] * sigm(vfr + 1.0f) + tanhf(vu) * sigm(vi);
        float hn = sigm(vo) * tanhf(cn);
        part += hn * wq[d];
    }
    __shared__ float red[8];
    for (int off = 16; off; off >>= 1) part += __shfl_down_sync(0xffffffffu, part, off);
    if ((threadIdx.x & 31) == 0) red[threadIdx.x >> 5] = part;
    __syncthreads();
    float s = 0.0f;
    if (threadIdx.x == 0)
        for (int w = 0; w < 8; w++) s += red[w];
    return s;
}

__global__ void k_pairinit(const int* __restrict__ len,
                           const float* __restrict__ bcomp, const float* __restrict__ wq) {
    int p = blockIdx.x, b = blockIdx.y;
    int ln = len[b];
    if (p > ln - 2) return;   // block-uniform
    float lg = pair_logit(b, g_seq[b][p], g_seq[b][p + 1], bcomp, wq);
    if (threadIdx.x == 0) g_logit[b][p] = lg;
}

// ---------------- per-iteration: argmax select + compose the chosen pair ----------------
__global__ void k_compose(int it, const int* __restrict__ len, const float* __restrict__ bcomp) {
    int b = blockIdx.x;
    int ln = len[b];
    if (ln - 1 <= it) {
        // inactive: zero the would-be new node so projection GEMM stays well-defined
        for (int d = threadIdx.x; d < D2; d += blockDim.x) g_nodeH[16 + it][b][d] = 0.0f;
        return;
    }
    __shared__ int sh[3];
    if (threadIdx.x == 0) {
        int vp = ln - 1 - it;               // remaining valid pairs
        int k = 0; float best = g_logit[b][0];
        for (int p = 1; p < vp; p++) {
            float v = g_logit[b][p];
            if (v > best) { best = v; k = p; }   // strict > = first-max tiebreak (matches argmax)
        }
        sh[0] = k; sh[1] = g_seq[b][k]; sh[2] = g_seq[b][k + 1];
    }
    __syncthreads();
    int k = sh[0], nl = sh[1], nr = sh[2];

    const float* pl = &g_PL[nl][b][0];
    const float* pr = &g_PR[nr][b][0];
    const float* cl = &g_nodeC[nl][b][0];
    const float* cr = &g_nodeC[nr][b][0];
    for (int d = threadIdx.x; d < D2; d += blockDim.x) {
        float vi  = pl[d]          + pr[d]          + bcomp[d];
        float vfl = pl[D2 + d]     + pr[D2 + d]     + bcomp[D2 + d];
        float vfr = pl[2 * D2 + d] + pr[2 * D2 + d] + bcomp[2 * D2 + d];
        float vu  = pl[3 * D2 + d] + pr[3 * D2 + d] + bcomp[3 * D2 + d];
        float vo  = pl[4 * D2 + d] + pr[4 * D2 + d] + bcomp[4 * D2 + d];
        float cn = cl[d] * sigm(vfl + 1.0f) + cr[d] * sigm(vfr + 1.0f) + tanhf(vu) * sigm(vi);
        float hn = sigm(vo) * tanhf(cn);
        g_nodeH[16 + it][b][d] = hn;
        g_nodeC[16 + it][b][d] = cn;
    }
    if (threadIdx.x == 0) {
        g_selpos[b] = k;
        for (int p = k + 1; p <= ln - 2 - it; p++) g_seq[b][p] = g_seq[b][p + 1];
        g_seq[b][k] = 16 + it;
        for (int p = k + 1; p <= ln - 3 - it; p++) g_logit[b][p] = g_logit[b][p + 1];
    }
}

// refresh the <=2 logits adjacent to the new node (after its projection GEMM)
__global__ void k_update(int it, const int* __restrict__ len,
                         const float* __restrict__ bcomp, const float* __restrict__ wq) {
    int b = blockIdx.y, q = blockIdx.x;       // q=0 -> pair k-1, q=1 -> pair k
    int ln = len[b];
    if (ln - 2 <= it) return;                 // no pairs remain for this batch
    int k = g_selpos[b];
    int p = k - 1 + q;
    if (p < 0) return;
    int np = ln - 2 - it;
    if (p >= np) return;
    float lg = pair_logit(b, g_seq[b][p], g_seq[b][p + 1], bcomp, wq);
    if (threadIdx.x == 0) g_logit[b][p] = lg;
}

__global__ void k_output(const int* __restrict__ len, float* __restrict__ out) {
    int idx = blockIdx.x * blockDim.x + threadIdx.x;
    if (idx >= B_ * D2) return;
    int b = idx >> 10;
    int d = idx & (D2 - 1);
    out[idx] = g_nodeH[14 + len[b]][b][d];    // root node id = 16 + (len-2)
}

// ---------------- orchestration ----------------
extern "C" void kernel_launch(void* const* d_in, const int* in_sizes, int n_in,
                              void* d_out, int out_size) {
    const float* x     = (const float*)d_in[0];
    const int*   len   = (const int*)  d_in[1];
    const float* wihf  = (const float*)d_in[2];
    const float* whhf  = (const float*)d_in[3];
    const float* bf    = (const float*)d_in[4];
    const float* wihb  = (const float*)d_in[5];
    const float* whhb  = (const float*)d_in[6];
    const float* bb    = (const float*)d_in[7];
    const float* wcomp = (const float*)d_in[8];
    const float* bcomp = (const float*)d_in[9];
    const float* wq    = (const float*)d_in[10];
    float* out = (float*)d_out;

    float *p_xg, *p_nH, *p_PL, *p_PR;
    int* p_rm;
    cudaGetSymbolAddress((void**)&p_xg,   g_xg);
    cudaGetSymbolAddress((void**)&p_nH,   g_nodeH);
    cudaGetSymbolAddress((void**)&p_PL,   g_PL);
    cudaGetSymbolAddress((void**)&p_PR,   g_PR);
    cudaGetSymbolAddress((void**)&p_rm,   g_rowmap);

    k_init<<<(2 * B_ * H_ + 255) / 256, 256>>>(len);

    // input projections: xg_f = x @ w_ih_f^T + b_f ; xg_b = gather(x) @ w_ih_b^T + b_b
    gemm_nt<128,128,16,8,8,256><<<dim3(G4/128, (B_*L_)/128), 256>>>(
        x, H_, nullptr, wihf, nullptr, H_, 0, bf, nullptr, 0,
        p_xg, nullptr, G4, H_);
    gemm_nt<128,128,16,8,8,256><<<dim3(G4/128, (B_*L_)/128), 256>>>(
        x, H_, p_rm, wihb, nullptr, H_, 0, bb, nullptr, 0,
        p_xg + (size_t)B_ * L_ * G4, nullptr, G4, H_);

    // 16 sequential LSTM steps: fused fwd+bwd recurrent GEMM, then gates
    for (int t = 0; t < L_; t++) {
        gemm_rec<<<dim3(G4/64, B_/64, 2), 256>>>(whhf, whhb, t);
        k_gates<<<(2 * B_ * H_ + 255) / 256, 256>>>(t, len);
    }

    // leaf projections: PL/PR for all 16 leaves in one split GEMM (N = 2*5120)
    gemm_nt<128,128,16,8,8,256><<<dim3((2*G5)/128, (16*B_)/128), 256>>>(
        p_nH, D2, nullptr, wcomp, wcomp + D2, 2 * D2, G5,
        nullptr, nullptr, 0, p_PL, p_PR, G5, D2);

    // initial pair logits
    k_pairinit<<<dim3(L_ - 1, B_), 256>>>(len, bcomp, wq);

    // 15 composition iterations
    for (int it = 0; it < L_ - 1; it++) {
        k_compose<<<B_, 256>>>(it, len, bcomp);
        if (it < L_ - 2) {
            gemm_nt<64,128,16,4,8,256><<<dim3((2*G5)/128, B_/64), 256>>>(
                p_nH + (size_t)(16 + it) * B_ * D2, D2, nullptr,
                wcomp, wcomp + D2, 2 * D2, G5,
                nullptr, nullptr, 0,
                p_PL + (size_t)(16 + it) * B_ * G5,
                p_PR + (size_t)(16 + it) * B_ * G5, G5, D2);
            k_update<<<dim3(2, B_), 256>>>(it, len, bcomp, wq);
        }
    }

    k_output<<<(B_ * D2 + 255) / 256, 256>>>(len, out);
}

// round 13
// speedup vs baseline: 1.2456x; 1.2395x over previous
#include <cuda_runtime.h>
#include <math.h>

#define B_  256
#define L_  16
#define H_  512
#define G4  2048      // 4*H
#define D2  1024      // 2*H
#define G5  5120      // 5*D2
#define NN  31        // 16 leaves + 15 internal nodes

// ---------------- scratch (static device globals; no allocation) ----------------
__device__ float g_xg[2][B_][L_][G4];      // input projections, fwd/bwd (bwd in reversed time order)
__device__ float g_gbuf[2][B_][G4];        // per-step gate pre-activations
__device__ float g_hst[2][B_][H_];         // running LSTM h
__device__ float g_cst[2][B_][H_];         // running LSTM c
__device__ float g_nodeH[NN][B_][D2];      // node h (node-major so GEMM rows are contiguous)
__device__ float g_nodeC[NN][B_][D2];      // node c
__device__ float g_PL[NN][B_][G5];         // cached h @ Wl^T
__device__ float g_PR[NN][B_][G5];         // cached h @ Wr^T
__device__ float g_logit[B_][L_];          // cached pair logits (current sequence order)
__device__ int   g_seq[B_][L_];            // current sequence -> node id
__device__ int   g_selpos[B_];             // selected pair position this iteration
__device__ int   g_rowmap[B_ * L_];        // row gather map for backward-LSTM input reversal

__device__ __forceinline__ float sigm(float x) { return 1.0f / (1.0f + expf(-x)); }

// ---------------- packed fp32x2 helpers (sm_103a 2x-rate fp32 path) ----------------
__device__ __forceinline__ unsigned long long pack2(float lo, float hi) {
    unsigned long long r;
    asm("mov.b64 %0, {%1, %2};" : "=l"(r)
        : "r"(__float_as_uint(lo)), "r"(__float_as_uint(hi)));
    return r;
}
__device__ __forceinline__ unsigned long long fma2(unsigned long long a,
                                                   unsigned long long b,
                                                   unsigned long long c) {
    unsigned long long d;
    asm("fma.rn.f32x2 %0, %1, %2, %3;" : "=l"(d) : "l"(a), "l"(b), "l"(c));
    return d;
}
__device__ __forceinline__ float2 unpack2(unsigned long long v) {
    unsigned int lo, hi;
    asm("mov.b64 {%0, %1}, %2;" : "=r"(lo), "=r"(hi) : "l"(v));
    return make_float2(__uint_as_float(lo), __uint_as_float(hi));
}

// 2-D warp-internal lane map: 8 distinct row-groups x 4 distinct col-groups per warp
// (vs 2x16 for the naive tid split) -> ~33-44% fewer distinct smem bytes per kk.
// Valid for all configs here: BM/TM == BN/TN == 16, NT == 256.
__device__ __forceinline__ void thread_map(int tid, int& ty, int& tx) {
    int wid = tid >> 5, lane = tid & 31;
    ty = ((wid >> 2) << 3) + (lane >> 2);   // (wid/4)*8 + lane/4   in [0,16)
    tx = ((wid & 3) << 2) + (lane & 3);     // (wid%4)*4 + lane%4   in [0,16)
}

// ---------------- init: zero LSTM state, build reversal map, seq identity ----------------
__global__ void k_init(const int* __restrict__ len) {
    int idx = blockIdx.x * blockDim.x + threadIdx.x;
    if (idx < 2 * B_ * H_) {
        ((float*)g_hst)[idx] = 0.0f;
        ((float*)g_cst)[idx] = 0.0f;
    }
    if (idx < B_ * L_) {
        int b = idx / L_, t = idx % L_;
        int ln = len[b];
        g_rowmap[idx] = b * L_ + ((t < ln) ? (ln - 1 - t) : t);
        g_seq[b][t] = t;
    }
}

// ---------------- generic fp32 NT GEMM, double-buffered + warp-2D lane map ---------------
// C[m][n] = sum_k A[m][k] * W[n][k] (+bias +add); fma.rn.f32x2 accumulation (bit-identical
// per lane to scalar fmaf, same kk order).
template<int BM, int BN, int BK, int TM, int TN, int NT>
__global__ void __launch_bounds__(NT) gemm_nt(
    const float* __restrict__ A, int lda, const int* __restrict__ rowmap,
    const float* __restrict__ W0, const float* __restrict__ W1, int ldw, int nsplit,
    const float* __restrict__ bias,
    const float* __restrict__ add, long long ldadd,
    float* __restrict__ C0, float* __restrict__ C1, int ldc,
    int K)
{
    static_assert(BM / TM == 16 && BN / TN == 16 && NT == 256, "thread_map contract");
    __shared__ float As[2][BK][BM];
    __shared__ float Ws[2][BK][BN];

    const int tid = threadIdx.x;
    const int n0 = blockIdx.x * BN;
    const int m0 = blockIdx.y * BM;

    const float* W = W0;
    float* C = C0;
    int nc0 = n0;
    if (nsplit > 0 && n0 >= nsplit) { W = W1; C = C1; nc0 = n0 - nsplit; }

    constexpr int TN2 = TN / 2;
    unsigned long long acc2[TM][TN2];
#pragma unroll
    for (int i = 0; i < TM; i++)
#pragma unroll
        for (int j = 0; j < TN2; j++) acc2[i][j] = 0ull;

    constexpr int KQ = BK / 4;                    // float4 slots along K
    constexpr int ALOAD = (BM * BK) / (4 * NT);
    constexpr int WLOAD = (BN * BK) / (4 * NT);

    int ty, tx;
    thread_map(tid, ty, tx);

    float4 av[ALOAD], wv[WLOAD];

    // prologue: load tile 0
#pragma unroll
    for (int i = 0; i < ALOAD; i++) {
        int e = tid + i * NT;
        int gr = m0 + e / KQ;
        int sr = rowmap ? rowmap[gr] : gr;
        av[i] = *reinterpret_cast<const float4*>(A + (size_t)sr * lda + (e % KQ) * 4);
    }
#pragma unroll
    for (int i = 0; i < WLOAD; i++) {
        int e = tid + i * NT;
        wv[i] = *reinterpret_cast<const float4*>(W + (size_t)(nc0 + e / KQ) * ldw + (e % KQ) * 4);
    }
#pragma unroll
    for (int i = 0; i < ALOAD; i++) {
        int e = tid + i * NT;
        int r = e / KQ, kq = (e % KQ) * 4;
        As[0][kq + 0][r] = av[i].x; As[0][kq + 1][r] = av[i].y;
        As[0][kq + 2][r] = av[i].z; As[0][kq + 3][r] = av[i].w;
    }
#pragma unroll
    for (int i = 0; i < WLOAD; i++) {
        int e = tid + i * NT;
        int r = e / KQ, kq = (e % KQ) * 4;
        Ws[0][kq + 0][r] = wv[i].x; Ws[0][kq + 1][r] = wv[i].y;
        Ws[0][kq + 2][r] = wv[i].z; Ws[0][kq + 3][r] = wv[i].w;
    }
    __syncthreads();

    const int KT = K / BK;
    for (int kt = 0; kt < KT; kt++) {
        const int cur = kt & 1;
        if (kt + 1 < KT) {
            int k0n = (kt + 1) * BK;
#pragma unroll
            for (int i = 0; i < ALOAD; i++) {
                int e = tid + i * NT;
                int gr = m0 + e / KQ;
                int sr = rowmap ? rowmap[gr] : gr;
                av[i] = *reinterpret_cast<const float4*>(A + (size_t)sr * lda + k0n + (e % KQ) * 4);
            }
#pragma unroll
            for (int i = 0; i < WLOAD; i++) {
                int e = tid + i * NT;
                wv[i] = *reinterpret_cast<const float4*>(W + (size_t)(nc0 + e / KQ) * ldw + k0n + (e % KQ) * 4);
            }
        }

#pragma unroll
        for (int kk = 0; kk < BK; kk++) {
            float ra[TM];
            unsigned long long rb2[TN2];
#pragma unroll
            for (int i = 0; i < TM; i += 4)
                *reinterpret_cast<float4*>(&ra[i]) =
                    *reinterpret_cast<const float4*>(&As[cur][kk][ty * TM + i]);
#pragma unroll
            for (int j = 0; j < TN2; j += 2) {
                ulonglong2 w2 = *reinterpret_cast<const ulonglong2*>(&Ws[cur][kk][tx * TN + j * 2]);
                rb2[j] = w2.x; rb2[j + 1] = w2.y;
            }
#pragma unroll
            for (int i = 0; i < TM; i++) {
                unsigned long long aa = pack2(ra[i], ra[i]);
#pragma unroll
                for (int j = 0; j < TN2; j++)
                    acc2[i][j] = fma2(aa, rb2[j], acc2[i][j]);
            }
        }

        if (kt + 1 < KT) {
            const int nxt = (kt + 1) & 1;
#pragma unroll
            for (int i = 0; i < ALOAD; i++) {
                int e = tid + i * NT;
                int r = e / KQ, kq = (e % KQ) * 4;
                As[nxt][kq + 0][r] = av[i].x; As[nxt][kq + 1][r] = av[i].y;
                As[nxt][kq + 2][r] = av[i].z; As[nxt][kq + 3][r] = av[i].w;
            }
#pragma unroll
            for (int i = 0; i < WLOAD; i++) {
                int e = tid + i * NT;
                int r = e / KQ, kq = (e % KQ) * 4;
                Ws[nxt][kq + 0][r] = wv[i].x; Ws[nxt][kq + 1][r] = wv[i].y;
                Ws[nxt][kq + 2][r] = wv[i].z; Ws[nxt][kq + 3][r] = wv[i].w;
            }
        }
        __syncthreads();
    }

#pragma unroll
    for (int i = 0; i < TM; i++) {
        size_t row = (size_t)(m0 + ty * TM + i);
#pragma unroll
        for (int j = 0; j < TN2; j++) {
            float2 v2 = unpack2(acc2[i][j]);
            int col = nc0 + tx * TN + j * 2;
            float v0 = v2.x, v1 = v2.y;
            if (bias) { v0 += bias[col]; v1 += bias[col + 1]; }
            if (add)  { v0 += add[row * (size_t)ldadd + col];
                        v1 += add[row * (size_t)ldadd + col + 1]; }
            C[row * (size_t)ldc + col]     = v0;
            C[row * (size_t)ldc + col + 1] = v1;
        }
    }
}

// ---------------- recurrent-step GEMM, both directions, double-buffered + 2D lane map -----
// gbuf[z] = hst[z] @ whh[z]^T + xg[z][:, t, :]  (blockIdx.z = direction)
__global__ void __launch_bounds__(256) gemm_rec(
    const float* __restrict__ whhf, const float* __restrict__ whhb, int t)
{
    constexpr int BM = 64, BN = 64, BK = 16, TM = 4, TN = 4;
    __shared__ float As[2][BK][BM];
    __shared__ float Ws[2][BK][BN];

    const int tid = threadIdx.x;
    const int n0 = blockIdx.x * BN;
    const int m0 = blockIdx.y * BM;
    const int z  = blockIdx.z;

    const float* A   = &g_hst[z][0][0];
    const float* W   = z ? whhb : whhf;
    const float* add = &g_xg[z][0][t][0];
    float*       C   = &g_gbuf[z][0][0];

    constexpr int TN2 = TN / 2;
    unsigned long long acc2[TM][TN2];
#pragma unroll
    for (int i = 0; i < TM; i++)
#pragma unroll
        for (int j = 0; j < TN2; j++) acc2[i][j] = 0ull;

    constexpr int KQ = BK / 4;
    int ty, tx;
    thread_map(tid, ty, tx);
    const int lr = tid / KQ;
    const int lk = (tid % KQ) * 4;

    float4 av, wv;
    av = *reinterpret_cast<const float4*>(A + (size_t)(m0 + lr) * H_ + lk);
    wv = *reinterpret_cast<const float4*>(W + (size_t)(n0 + lr) * H_ + lk);
    As[0][lk + 0][lr] = av.x; As[0][lk + 1][lr] = av.y; As[0][lk + 2][lr] = av.z; As[0][lk + 3][lr] = av.w;
    Ws[0][lk + 0][lr] = wv.x; Ws[0][lk + 1][lr] = wv.y; Ws[0][lk + 2][lr] = wv.z; Ws[0][lk + 3][lr] = wv.w;
    __syncthreads();

    const int KT = H_ / BK;
    for (int kt = 0; kt < KT; kt++) {
        const int cur = kt & 1;
        if (kt + 1 < KT) {
            int k0n = (kt + 1) * BK;
            av = *reinterpret_cast<const float4*>(A + (size_t)(m0 + lr) * H_ + k0n + lk);
            wv = *reinterpret_cast<const float4*>(W + (size_t)(n0 + lr) * H_ + k0n + lk);
        }

#pragma unroll
        for (int kk = 0; kk < BK; kk++) {
            float ra[TM];
            unsigned long long rb2[TN2];
            *reinterpret_cast<float4*>(&ra[0]) =
                *reinterpret_cast<const float4*>(&As[cur][kk][ty * TM]);
            {
                ulonglong2 w2 = *reinterpret_cast<const ulonglong2*>(&Ws[cur][kk][tx * TN]);
                rb2[0] = w2.x; rb2[1] = w2.y;
            }
#pragma unroll
            for (int i = 0; i < TM; i++) {
                unsigned long long aa = pack2(ra[i], ra[i]);
#pragma unroll
                for (int j = 0; j < TN2; j++)
                    acc2[i][j] = fma2(aa, rb2[j], acc2[i][j]);
            }
        }

        if (kt + 1 < KT) {
            const int nxt = (kt + 1) & 1;
            As[nxt][lk + 0][lr] = av.x; As[nxt][lk + 1][lr] = av.y;
            As[nxt][lk + 2][lr] = av.z; As[nxt][lk + 3][lr] = av.w;
            Ws[nxt][lk + 0][lr] = wv.x; Ws[nxt][lk + 1][lr] = wv.y;
            Ws[nxt][lk + 2][lr] = wv.z; Ws[nxt][lk + 3][lr] = wv.w;
        }
        __syncthreads();
    }

#pragma unroll
    for (int i = 0; i < TM; i++) {
        size_t row = (size_t)(m0 + ty * TM + i);
#pragma unroll
        for (int j = 0; j < TN2; j++) {
            float2 v2 = unpack2(acc2[i][j]);
            int col = n0 + tx * TN + j * 2;
            C[row * G4 + col]     = v2.x + add[row * (size_t)(L_ * G4) + col];
            C[row * G4 + col + 1] = v2.y + add[row * (size_t)(L_ * G4) + col + 1];
        }
    }
}

// ---------------- LSTM gate elementwise (both directions), writes leaves ----------------
__global__ void k_gates(int t, const int* __restrict__ len) {
    int idx = blockIdx.x * blockDim.x + threadIdx.x;
    if (idx >= 2 * B_ * H_) return;
    int d = idx >> 17;                    // B_*H_ = 131072 = 1<<17
    int r = idx & ((1 << 17) - 1);
    int b = r >> 9;                       // H_ = 512 = 1<<9
    int j = r & (H_ - 1);

    const float* gb = &g_gbuf[d][b][0];
    float gi = gb[j];
    float gf = gb[H_ + j];
    float gu = gb[2 * H_ + j];
    float go = gb[3 * H_ + j];
    float cp = g_cst[d][b][j];
    float cn = sigm(gf) * cp + sigm(gi) * tanhf(gu);
    float hn = sigm(go) * tanhf(cn);
    g_cst[d][b][j] = cn;
    g_hst[d][b][j] = hn;

    int ln = len[b];
    int pos = (d == 0) ? t : ((t < ln) ? (ln - 1 - t) : t);
    g_nodeH[pos][b][d * H_ + j] = hn;
    g_nodeC[pos][b][d * H_ + j] = cn;
}

// ---------------- pair logit from cached projections (block-collective, 256 threads) --------
__device__ float pair_logit(int b, int nl, int nr,
                            const float* __restrict__ bcomp, const float* __restrict__ wq)
{
    const float* pl = &g_PL[nl][b][0];
    const float* pr = &g_PR[nr][b][0];
    const float* cl = &g_nodeC[nl][b][0];
    const float* cr = &g_nodeC[nr][b][0];
    float part = 0.0f;
    for (int d = threadIdx.x; d < D2; d += blockDim.x) {
        float vi  = pl[d]          + pr[d]          + bcomp[d];
        float vfl = pl[D2 + d]     + pr[D2 + d]     + bcomp[D2 + d];
        float vfr = pl[2 * D2 + d] + pr[2 * D2 + d] + bcomp[2 * D2 + d];
        float vu  = pl[3 * D2 + d] + pr[3 * D2 + d] + bcomp[3 * D2 + d];
        float vo  = pl[4 * D2 + d] + pr[4 * D2 + d] + bcomp[4 * D2 + d];
        float cn = cl[d] * sigm(vfl + 1.0f) + cr[d] * sigm(vfr + 1.0f) + tanhf(vu) * sigm(vi);
        float hn = sigm(vo) * tanhf(cn);
        part += hn * wq[d];
    }
    __shared__ float red[8];
    for (int off = 16; off; off >>= 1) part += __shfl_down_sync(0xffffffffu, part, off);
    if ((threadIdx.x & 31) == 0) red[threadIdx.x >> 5] = part;
    __syncthreads();
    float s = 0.0f;
    if (threadIdx.x == 0)
        for (int w = 0; w < 8; w++) s += red[w];
    return s;
}

__global__ void k_pairinit(const int* __restrict__ len,
                           const float* __restrict__ bcomp, const float* __restrict__ wq) {
    int p = blockIdx.x, b = blockIdx.y;
    int ln = len[b];
    if (p > ln - 2) return;   // block-uniform
    float lg = pair_logit(b, g_seq[b][p], g_seq[b][p + 1], bcomp, wq);
    if (threadIdx.x == 0) g_logit[b][p] = lg;
}

// ---------------- per-iteration: argmax select + compose the chosen pair ----------------
__global__ void k_compose(int it, const int* __restrict__ len, const float* __restrict__ bcomp) {
    int b = blockIdx.x;
    int ln = len[b];
    if (ln - 1 <= it) {
        // inactive: zero the would-be new node so projection GEMM stays well-defined
        for (int d = threadIdx.x; d < D2; d += blockDim.x) g_nodeH[16 + it][b][d] = 0.0f;
        return;
    }
    __shared__ int sh[3];
    if (threadIdx.x == 0) {
        int vp = ln - 1 - it;               // remaining valid pairs
        int k = 0; float best = g_logit[b][0];
        for (int p = 1; p < vp; p++) {
            float v = g_logit[b][p];
            if (v > best) { best = v; k = p; }   // strict > = first-max tiebreak (matches argmax)
        }
        sh[0] = k; sh[1] = g_seq[b][k]; sh[2] = g_seq[b][k + 1];
    }
    __syncthreads();
    int k = sh[0], nl = sh[1], nr = sh[2];

    const float* pl = &g_PL[nl][b][0];
    const float* pr = &g_PR[nr][b][0];
    const float* cl = &g_nodeC[nl][b][0];
    const float* cr = &g_nodeC[nr][b][0];
    for (int d = threadIdx.x; d < D2; d += blockDim.x) {
        float vi  = pl[d]          + pr[d]          + bcomp[d];
        float vfl = pl[D2 + d]     + pr[D2 + d]     + bcomp[D2 + d];
        float vfr = pl[2 * D2 + d] + pr[2 * D2 + d] + bcomp[2 * D2 + d];
        float vu  = pl[3 * D2 + d] + pr[3 * D2 + d] + bcomp[3 * D2 + d];
        float vo  = pl[4 * D2 + d] + pr[4 * D2 + d] + bcomp[4 * D2 + d];
        float cn = cl[d] * sigm(vfl + 1.0f) + cr[d] * sigm(vfr + 1.0f) + tanhf(vu) * sigm(vi);
        float hn = sigm(vo) * tanhf(cn);
        g_nodeH[16 + it][b][d] = hn;
        g_nodeC[16 + it][b][d] = cn;
    }
    if (threadIdx.x == 0) {
        g_selpos[b] = k;
        for (int p = k + 1; p <= ln - 2 - it; p++) g_seq[b][p] = g_seq[b][p + 1];
        g_seq[b][k] = 16 + it;
        for (int p = k + 1; p <= ln - 3 - it; p++) g_logit[b][p] = g_logit[b][p + 1];
    }
}

// refresh the <=2 logits adjacent to the new node (after its projection GEMM)
__global__ void k_update(int it, const int* __restrict__ len,
                         const float* __restrict__ bcomp, const float* __restrict__ wq) {
    int b = blockIdx.y, q = blockIdx.x;       // q=0 -> pair k-1, q=1 -> pair k
    int ln = len[b];
    if (ln - 2 <= it) return;                 // no pairs remain for this batch
    int k = g_selpos[b];
    int p = k - 1 + q;
    if (p < 0) return;
    int np = ln - 2 - it;
    if (p >= np) return;
    float lg = pair_logit(b, g_seq[b][p], g_seq[b][p + 1], bcomp, wq);
    if (threadIdx.x == 0) g_logit[b][p] = lg;
}

__global__ void k_output(const int* __restrict__ len, float* __restrict__ out) {
    int idx = blockIdx.x * blockDim.x + threadIdx.x;
    if (idx >= B_ * D2) return;
    int b = idx >> 10;
    int d = idx & (D2 - 1);
    out[idx] = g_nodeH[14 + len[b]][b][d];    // root node id = 16 + (len-2)
}

// ---------------- orchestration ----------------
extern "C" void kernel_launch(void* const* d_in, const int* in_sizes, int n_in,
                              void* d_out, int out_size) {
    const float* x     = (const float*)d_in[0];
    const int*   len   = (const int*)  d_in[1];
    const float* wihf  = (const float*)d_in[2];
    const float* whhf  = (const float*)d_in[3];
    const float* bf    = (const float*)d_in[4];
    const float* wihb  = (const float*)d_in[5];
    const float* whhb  = (const float*)d_in[6];
    const float* bb    = (const float*)d_in[7];
    const float* wcomp = (const float*)d_in[8];
    const float* bcomp = (const float*)d_in[9];
    const float* wq    = (const float*)d_in[10];
    float* out = (float*)d_out;

    float *p_xg, *p_nH, *p_PL, *p_PR;
    int* p_rm;
    cudaGetSymbolAddress((void**)&p_xg,   g_xg);
    cudaGetSymbolAddress((void**)&p_nH,   g_nodeH);
    cudaGetSymbolAddress((void**)&p_PL,   g_PL);
    cudaGetSymbolAddress((void**)&p_PR,   g_PR);
    cudaGetSymbolAddress((void**)&p_rm,   g_rowmap);

    k_init<<<(2 * B_ * H_ + 255) / 256, 256>>>(len);

    // input projections: xg_f = x @ w_ih_f^T + b_f ; xg_b = gather(x) @ w_ih_b^T + b_b
    gemm_nt<128,128,16,8,8,256><<<dim3(G4/128, (B_*L_)/128), 256>>>(
        x, H_, nullptr, wihf, nullptr, H_, 0, bf, nullptr, 0,
        p_xg, nullptr, G4, H_);
    gemm_nt<128,128,16,8,8,256><<<dim3(G4/128, (B_*L_)/128), 256>>>(
        x, H_, p_rm, wihb, nullptr, H_, 0, bb, nullptr, 0,
        p_xg + (size_t)B_ * L_ * G4, nullptr, G4, H_);

    // 16 sequential LSTM steps: fused fwd+bwd recurrent GEMM, then gates
    for (int t = 0; t < L_; t++) {
        gemm_rec<<<dim3(G4/64, B_/64, 2), 256>>>(whhf, whhb, t);
        k_gates<<<(2 * B_ * H_ + 255) / 256, 256>>>(t, len);
    }

    // leaf projections: PL/PR for all 16 leaves in one split GEMM (N = 2*5120)
    gemm_nt<128,128,16,8,8,256><<<dim3((2*G5)/128, (16*B_)/128), 256>>>(
        p_nH, D2, nullptr, wcomp, wcomp + D2, 2 * D2, G5,
        nullptr, nullptr, 0, p_PL, p_PR, G5, D2);

    // initial pair logits
    k_pairinit<<<dim3(L_ - 1, B_), 256>>>(len, bcomp, wq);

    // 15 composition iterations
    for (int it = 0; it < L_ - 1; it++) {
        k_compose<<<B_, 256>>>(it, len, bcomp);
        if (it < L_ - 2) {
            gemm_nt<64,128,16,4,8,256><<<dim3((2*G5)/128, B_/64), 256>>>(
                p_nH + (size_t)(16 + it) * B_ * D2, D2, nullptr,
                wcomp, wcomp + D2, 2 * D2, G5,
                nullptr, nullptr, 0,
                p_PL + (size_t)(16 + it) * B_ * G5,
                p_PR + (size_t)(16 + it) * B_ * G5, G5, D2);
            k_update<<<dim3(2, B_), 256>>>(it, len, bcomp, wq);
        }
    }

    k_output<<<(B_ * D2 + 255) / 256, 256>>>(len, out);
}

// round 17
// speedup vs baseline: 1.7232x; 1.3834x over previous
#include <cuda_runtime.h>
#include <math.h>

#define B_  256
#define L_  16
#define H_  512
#define G4  2048      // 4*H
#define D2  1024      // 2*H
#define G5  5120      // 5*D2
#define NN  31        // 16 leaves + 15 internal nodes
#define NIT 14        // iterations with a projection GEMM (it < L_-2)

// ---------------- scratch (static device globals; no allocation) ----------------
__device__ float g_xg[2][B_][L_][G4];      // input projections, fwd/bwd (bwd in reversed time order)
__device__ float g_gbuf[2][B_][G4];        // per-step gate pre-activations
__device__ float g_hst[2][B_][H_];         // running LSTM h
__device__ float g_cst[2][B_][H_];         // running LSTM c
__device__ float g_nodeH[NN][B_][D2];      // node h (node-major so GEMM rows are contiguous)
__device__ float g_nodeC[NN][B_][D2];      // node c
__device__ float g_PL[NN][B_][G5];         // cached h @ Wl^T
__device__ float g_PR[NN][B_][G5];         // cached h @ Wr^T
__device__ float g_logit[B_][L_];          // cached pair logits (current sequence order)
__device__ int   g_seq[B_][L_];            // current sequence -> node id
__device__ int   g_selpos[B_];             // selected pair position this iteration
__device__ int   g_rowmap[B_ * L_];        // row gather map for backward-LSTM input reversal

// projection-row compaction: permutations with active rows first + active counts
__device__ int   g_lalist[B_ * L_];        // leaf rows (flat pos*B_+b), active-first
__device__ int   g_lacnt, g_ltcnt;
__device__ int   g_italist[NIT][B_];       // per-iteration batch lists, active-first
__device__ int   g_iacnt[NIT], g_itcnt[NIT];

__device__ __forceinline__ float sigm(float x) { return 1.0f / (1.0f + expf(-x)); }

// ---------------- packed fp32x2 helpers (sm_103a 2x-rate fp32 path) ----------------
__device__ __forceinline__ unsigned long long pack2(float lo, float hi) {
    unsigned long long r;
    asm("mov.b64 %0, {%1, %2};" : "=l"(r)
        : "r"(__float_as_uint(lo)), "r"(__float_as_uint(hi)));
    return r;
}
__device__ __forceinline__ unsigned long long fma2(unsigned long long a,
                                                   unsigned long long b,
                                                   unsigned long long c) {
    unsigned long long d;
    asm("fma.rn.f32x2 %0, %1, %2, %3;" : "=l"(d) : "l"(a), "l"(b), "l"(c));
    return d;
}
__device__ __forceinline__ float2 unpack2(unsigned long long v) {
    unsigned int lo, hi;
    asm("mov.b64 {%0, %1}, %2;" : "=r"(lo), "=r"(hi) : "l"(v));
    return make_float2(__uint_as_float(lo), __uint_as_float(hi));
}

// 2-D warp-internal lane map: 8 distinct row-groups x 4 distinct col-groups per warp.
__device__ __forceinline__ void thread_map(int tid, int& ty, int& tx) {
    int wid = tid >> 5, lane = tid & 31;
    ty = ((wid >> 2) << 3) + (lane >> 2);   // in [0,16)
    tx = ((wid & 3) << 2) + (lane & 3);     // in [0,16)
}

// ---------------- counter reset (must precede k_init's atomics; re-runs every replay) ------
__global__ void k_reset() {
    int i = threadIdx.x;
    if (i == 0) { g_lacnt = 0; g_ltcnt = B_ * L_; }
    if (i < NIT) { g_iacnt[i] = 0; g_itcnt[i] = B_; }
}

// ---------------- init: zero LSTM state, reversal map, seq identity, leaf active list -------
__global__ void k_init(const int* __restrict__ len) {
    int idx = blockIdx.x * blockDim.x + threadIdx.x;
    if (idx < 2 * B_ * H_) {
        ((float*)g_hst)[idx] = 0.0f;
        ((float*)g_cst)[idx] = 0.0f;
    }
    if (idx < B_ * L_) {
        int b = idx / L_, t = idx % L_;
        int ln = len[b];
        g_rowmap[idx] = b * L_ + ((t < ln) ? (ln - 1 - t) : t);
        g_seq[b][t] = t;
        int row = t * B_ + b;               // flat row in g_nodeH / g_PL / g_PR
        if (t < ln) { int s = atomicAdd(&g_lacnt, 1); g_lalist[s] = row; }
        else        { int s = atomicSub(&g_ltcnt, 1) - 1; g_lalist[s] = row; }
    }
}

// ---------------- generic fp32 NT GEMM, double-buffered + warp-2D lane map ---------------
// C[m][n] = sum_k A[m][k] * W[n][k] (+bias +add); fma.rn.f32x2 accumulation.
// rowmap: load-only row gather (bwd input reversal).
// outmap/nactp: load+store row gather with block early-exit (projection compaction);
//   blocks with m0 >= *nactp skip entirely — their output rows are never read.
template<int BM, int BN, int BK, int TM, int TN, int NT>
__global__ void __launch_bounds__(NT) gemm_nt(
    const float* __restrict__ A, int lda, const int* __restrict__ rowmap,
    const int* __restrict__ outmap, const int* __restrict__ nactp,
    const float* __restrict__ W0, const float* __restrict__ W1, int ldw, int nsplit,
    const float* __restrict__ bias,
    const float* __restrict__ add, long long ldadd,
    float* __restrict__ C0, float* __restrict__ C1, int ldc,
    int K)
{
    static_assert(BM / TM == 16 && BN / TN == 16 && NT == 256, "thread_map contract");
    __shared__ float As[2][BK][BM];
    __shared__ float Ws[2][BK][BN];

    const int tid = threadIdx.x;
    const int n0 = blockIdx.x * BN;
    const int m0 = blockIdx.y * BM;

    if (nactp && m0 >= *nactp) return;      // whole block maps to never-read rows

    const float* W = W0;
    float* C = C0;
    int nc0 = n0;
    if (nsplit > 0 && n0 >= nsplit) { W = W1; C = C1; nc0 = n0 - nsplit; }

    constexpr int TN2 = TN / 2;
    unsigned long long acc2[TM][TN2];
#pragma unroll
    for (int i = 0; i < TM; i++)
#pragma unroll
        for (int j = 0; j < TN2; j++) acc2[i][j] = 0ull;

    constexpr int KQ = BK / 4;                    // float4 slots along K
    constexpr int ALOAD = (BM * BK) / (4 * NT);
    constexpr int WLOAD = (BN * BK) / (4 * NT);

    int ty, tx;
    thread_map(tid, ty, tx);

    float4 av[ALOAD], wv[WLOAD];

    // prologue: load tile 0
#pragma unroll
    for (int i = 0; i < ALOAD; i++) {
        int e = tid + i * NT;
        int gr = m0 + e / KQ;
        int sr = outmap ? outmap[gr] : (rowmap ? rowmap[gr] : gr);
        av[i] = *reinterpret_cast<const float4*>(A + (size_t)sr * lda + (e % KQ) * 4);
    }
#pragma unroll
    for (int i = 0; i < WLOAD; i++) {
        int e = tid + i * NT;
        wv[i] = *reinterpret_cast<const float4*>(W + (size_t)(nc0 + e / KQ) * ldw + (e % KQ) * 4);
    }
#pragma unroll
    for (int i = 0; i < ALOAD; i++) {
        int e = tid + i * NT;
        int r = e / KQ, kq = (e % KQ) * 4;
        As[0][kq + 0][r] = av[i].x; As[0][kq + 1][r] = av[i].y;
        As[0][kq + 2][r] = av[i].z; As[0][kq + 3][r] = av[i].w;
    }
#pragma unroll
    for (int i = 0; i < WLOAD; i++) {
        int e = tid + i * NT;
        int r = e / KQ, kq = (e % KQ) * 4;
        Ws[0][kq + 0][r] = wv[i].x; Ws[0][kq + 1][r] = wv[i].y;
        Ws[0][kq + 2][r] = wv[i].z; Ws[0][kq + 3][r] = wv[i].w;
    }
    __syncthreads();

    const int KT = K / BK;
    for (int kt = 0; kt < KT; kt++) {
        const int cur = kt & 1;
        if (kt + 1 < KT) {
            int k0n = (kt + 1) * BK;
#pragma unroll
            for (int i = 0; i < ALOAD; i++) {
                int e = tid + i * NT;
                int gr = m0 + e / KQ;
                int sr = outmap ? outmap[gr] : (rowmap ? rowmap[gr] : gr);
                av[i] = *reinterpret_cast<const float4*>(A + (size_t)sr * lda + k0n + (e % KQ) * 4);
            }
#pragma unroll
            for (int i = 0; i < WLOAD; i++) {
                int e = tid + i * NT;
                wv[i] = *reinterpret_cast<const float4*>(W + (size_t)(nc0 + e / KQ) * ldw + k0n + (e % KQ) * 4);
            }
        }

#pragma unroll
        for (int kk = 0; kk < BK; kk++) {
            float ra[TM];
            unsigned long long rb2[TN2];
#pragma unroll
            for (int i = 0; i < TM; i += 4)
                *reinterpret_cast<float4*>(&ra[i]) =
                    *reinterpret_cast<const float4*>(&As[cur][kk][ty * TM + i]);
#pragma unroll
            for (int j = 0; j < TN2; j += 2) {
                ulonglong2 w2 = *reinterpret_cast<const ulonglong2*>(&Ws[cur][kk][tx * TN + j * 2]);
                rb2[j] = w2.x; rb2[j + 1] = w2.y;
            }
#pragma unroll
            for (int i = 0; i < TM; i++) {
                unsigned long long aa = pack2(ra[i], ra[i]);
#pragma unroll
                for (int j = 0; j < TN2; j++)
                    acc2[i][j] = fma2(aa, rb2[j], acc2[i][j]);
            }
        }

        if (kt + 1 < KT) {
            const int nxt = (kt + 1) & 1;
#pragma unroll
            for (int i = 0; i < ALOAD; i++) {
                int e = tid + i * NT;
                int r = e / KQ, kq = (e % KQ) * 4;
                As[nxt][kq + 0][r] = av[i].x; As[nxt][kq + 1][r] = av[i].y;
                As[nxt][kq + 2][r] = av[i].z; As[nxt][kq + 3][r] = av[i].w;
            }
#pragma unroll
            for (int i = 0; i < WLOAD; i++) {
                int e = tid + i * NT;
                int r = e / KQ, kq = (e % KQ) * 4;
                Ws[nxt][kq + 0][r] = wv[i].x; Ws[nxt][kq + 1][r] = wv[i].y;
                Ws[nxt][kq + 2][r] = wv[i].z; Ws[nxt][kq + 3][r] = wv[i].w;
            }
        }
        __syncthreads();
    }

#pragma unroll
    for (int i = 0; i < TM; i++) {
        int srow = m0 + ty * TM + i;
        size_t row = outmap ? (size_t)outmap[srow] : (size_t)srow;
#pragma unroll
        for (int j = 0; j < TN2; j++) {
            float2 v2 = unpack2(acc2[i][j]);
            int col = nc0 + tx * TN + j * 2;
            float v0 = v2.x, v1 = v2.y;
            if (bias) { v0 += bias[col]; v1 += bias[col + 1]; }
            if (add)  { v0 += add[row * (size_t)ldadd + col];
                        v1 += add[row * (size_t)ldadd + col + 1]; }
            C[row * (size_t)ldc + col]     = v0;
            C[row * (size_t)ldc + col + 1] = v1;
        }
    }
}

// ---------------- recurrent-step GEMM, both directions, double-buffered + 2D lane map -----
__global__ void __launch_bounds__(256) gemm_rec(
    const float* __restrict__ whhf, const float* __restrict__ whhb, int t)
{
    constexpr int BM = 64, BN = 64, BK = 16, TM = 4, TN = 4;
    __shared__ float As[2][BK][BM];
    __shared__ float Ws[2][BK][BN];

    const int tid = threadIdx.x;
    const int n0 = blockIdx.x * BN;
    const int m0 = blockIdx.y * BM;
    const int z  = blockIdx.z;

    const float* A   = &g_hst[z][0][0];
    const float* W   = z ? whhb : whhf;
    const float* add = &g_xg[z][0][t][0];
    float*       C   = &g_gbuf[z][0][0];

    constexpr int TN2 = TN / 2;
    unsigned long long acc2[TM][TN2];
#pragma unroll
    for (int i = 0; i < TM; i++)
#pragma unroll
        for (int j = 0; j < TN2; j++) acc2[i][j] = 0ull;

    constexpr int KQ = BK / 4;
    int ty, tx;
    thread_map(tid, ty, tx);
    const int lr = tid / KQ;
    const int lk = (tid % KQ) * 4;

    float4 av, wv;
    av = *reinterpret_cast<const float4*>(A + (size_t)(m0 + lr) * H_ + lk);
    wv = *reinterpret_cast<const float4*>(W + (size_t)(n0 + lr) * H_ + lk);
    As[0][lk + 0][lr] = av.x; As[0][lk + 1][lr] = av.y; As[0][lk + 2][lr] = av.z; As[0][lk + 3][lr] = av.w;
    Ws[0][lk + 0][lr] = wv.x; Ws[0][lk + 1][lr] = wv.y; Ws[0][lk + 2][lr] = wv.z; Ws[0][lk + 3][lr] = wv.w;
    __syncthreads();

    const int KT = H_ / BK;
    for (int kt = 0; kt < KT; kt++) {
        const int cur = kt & 1;
        if (kt + 1 < KT) {
            int k0n = (kt + 1) * BK;
            av = *reinterpret_cast<const float4*>(A + (size_t)(m0 + lr) * H_ + k0n + lk);
            wv = *reinterpret_cast<const float4*>(W + (size_t)(n0 + lr) * H_ + k0n + lk);
        }

#pragma unroll
        for (int kk = 0; kk < BK; kk++) {
            float ra[TM];
            unsigned long long rb2[TN2];
            *reinterpret_cast<float4*>(&ra[0]) =
                *reinterpret_cast<const float4*>(&As[cur][kk][ty * TM]);
            {
                ulonglong2 w2 = *reinterpret_cast<const ulonglong2*>(&Ws[cur][kk][tx * TN]);
                rb2[0] = w2.x; rb2[1] = w2.y;
            }
#pragma unroll
            for (int i = 0; i < TM; i++) {
                unsigned long long aa = pack2(ra[i], ra[i]);
#pragma unroll
                for (int j = 0; j < TN2; j++)
                    acc2[i][j] = fma2(aa, rb2[j], acc2[i][j]);
            }
        }

        if (kt + 1 < KT) {
            const int nxt = (kt + 1) & 1;
            As[nxt][lk + 0][lr] = av.x; As[nxt][lk + 1][lr] = av.y;
            As[nxt][lk + 2][lr] = av.z; As[nxt][lk + 3][lr] = av.w;
            Ws[nxt][lk + 0][lr] = wv.x; Ws[nxt][lk + 1][lr] = wv.y;
            Ws[nxt][lk + 2][lr] = wv.z; Ws[nxt][lk + 3][lr] = wv.w;
        }
        __syncthreads();
    }

#pragma unroll
    for (int i = 0; i < TM; i++) {
        size_t row = (size_t)(m0 + ty * TM + i);
#pragma unroll
        for (int j = 0; j < TN2; j++) {
            float2 v2 = unpack2(acc2[i][j]);
            int col = n0 + tx * TN + j * 2;
            C[row * G4 + col]     = v2.x + add[row * (size_t)(L_ * G4) + col];
            C[row * G4 + col + 1] = v2.y + add[row * (size_t)(L_ * G4) + col + 1];
        }
    }
}

// ---------------- LSTM gate elementwise (both directions), writes leaves ----------------
__global__ void k_gates(int t, const int* __restrict__ len) {
    int idx = blockIdx.x * blockDim.x + threadIdx.x;
    if (idx >= 2 * B_ * H_) return;
    int d = idx >> 17;
    int r = idx & ((1 << 17) - 1);
    int b = r >> 9;
    int j = r & (H_ - 1);

    const float* gb = &g_gbuf[d][b][0];
    float gi = gb[j];
    float gf = gb[H_ + j];
    float gu = gb[2 * H_ + j];
    float go = gb[3 * H_ + j];
    float cp = g_cst[d][b][j];
    float cn = sigm(gf) * cp + sigm(gi) * tanhf(gu);
    float hn = sigm(go) * tanhf(cn);
    g_cst[d][b][j] = cn;
    g_hst[d][b][j] = hn;

    int ln = len[b];
    int pos = (d == 0) ? t : ((t < ln) ? (ln - 1 - t) : t);
    g_nodeH[pos][b][d * H_ + j] = hn;
    g_nodeC[pos][b][d * H_ + j] = cn;
}

// ---------------- pair logit from cached projections (block-collective, 256 threads) --------
__device__ float pair_logit(int b, int nl, int nr,
                            const float* __restrict__ bcomp, const float* __restrict__ wq)
{
    const float* pl = &g_PL[nl][b][0];
    const float* pr = &g_PR[nr][b][0];
    const float* cl = &g_nodeC[nl][b][0];
    const float* cr = &g_nodeC[nr][b][0];
    float part = 0.0f;
    for (int d = threadIdx.x; d < D2; d += blockDim.x) {
        float vi  = pl[d]          + pr[d]          + bcomp[d];
        float vfl = pl[D2 + d]     + pr[D2 + d]     + bcomp[D2 + d];
        float vfr = pl[2 * D2 + d] + pr[2 * D2 + d] + bcomp[2 * D2 + d];
        float vu  = pl[3 * D2 + d] + pr[3 * D2 + d] + bcomp[3 * D2 + d];
        float vo  = pl[4 * D2 + d] + pr[4 * D2 + d] + bcomp[4 * D2 + d];
        float cn = cl[d] * sigm(vfl + 1.0f) + cr[d] * sigm(vfr + 1.0f) + tanhf(vu) * sigm(vi);
        float hn = sigm(vo) * tanhf(cn);
        part += hn * wq[d];
    }
    __shared__ float red[8];
    for (int off = 16; off; off >>= 1) part += __shfl_down_sync(0xffffffffu, part, off);
    if ((threadIdx.x & 31) == 0) red[threadIdx.x >> 5] = part;
    __syncthreads();
    float s = 0.0f;
    if (threadIdx.x == 0)
        for (int w = 0; w < 8; w++) s += red[w];
    return s;
}

__global__ void k_pairinit(const int* __restrict__ len,
                           const float* __restrict__ bcomp, const float* __restrict__ wq) {
    int p = blockIdx.x, b = blockIdx.y;
    int ln = len[b];
    if (p > ln - 2) return;
    float lg = pair_logit(b, g_seq[b][p], g_seq[b][p + 1], bcomp, wq);
    if (threadIdx.x == 0) g_logit[b][p] = lg;
}

// ---------------- per-iteration: argmax select + compose + active-list registration ---------
__global__ void k_compose(int it, const int* __restrict__ len, const float* __restrict__ bcomp) {
    int b = blockIdx.x;
    int ln = len[b];
    if (ln - 1 <= it) {
        if (threadIdx.x == 0 && it < NIT) {              // register inactive (tail)
            int s = atomicSub(&g_itcnt[it], 1) - 1;
            g_italist[it][s] = b;
        }
        // keep node row defined (cheap; rows are skipped by the GEMM anyway)
        for (int d = threadIdx.x; d < D2; d += blockDim.x) g_nodeH[16 + it][b][d] = 0.0f;
        return;
    }
    __shared__ int sh[3];
    if (threadIdx.x == 0) {
        int vp = ln - 1 - it;
        int k = 0; float best = g_logit[b][0];
        for (int p = 1; p < vp; p++) {
            float v = g_logit[b][p];
            if (v > best) { best = v; k = p; }
        }
        sh[0] = k; sh[1] = g_seq[b][k]; sh[2] = g_seq[b][k + 1];
        if (it < NIT) {                                   // register active (front)
            int s = atomicAdd(&g_iacnt[it], 1);
            g_italist[it][s] = b;
        }
    }
    __syncthreads();
    int k = sh[0], nl = sh[1], nr = sh[2];

    const float* pl = &g_PL[nl][b][0];
    const float* pr = &g_PR[nr][b][0];
    const float* cl = &g_nodeC[nl][b][0];
    const float* cr = &g_nodeC[nr][b][0];
    for (int d = threadIdx.x; d < D2; d += blockDim.x) {
        float vi  = pl[d]          + pr[d]          + bcomp[d];
        float vfl = pl[D2 + d]     + pr[D2 + d]     + bcomp[D2 + d];
        float vfr = pl[2 * D2 + d] + pr[2 * D2 + d] + bcomp[2 * D2 + d];
        float vu  = pl[3 * D2 + d] + pr[3 * D2 + d] + bcomp[3 * D2 + d];
        float vo  = pl[4 * D2 + d] + pr[4 * D2 + d] + bcomp[4 * D2 + d];
        float cn = cl[d] * sigm(vfl + 1.0f) + cr[d] * sigm(vfr + 1.0f) + tanhf(vu) * sigm(vi);
        float hn = sigm(vo) * tanhf(cn);
        g_nodeH[16 + it][b][d] = hn;
        g_nodeC[16 + it][b][d] = cn;
    }
    if (threadIdx.x == 0) {
        g_selpos[b] = k;
        for (int p = k + 1; p <= ln - 2 - it; p++) g_seq[b][p] = g_seq[b][p + 1];
        g_seq[b][k] = 16 + it;
        for (int p = k + 1; p <= ln - 3 - it; p++) g_logit[b][p] = g_logit[b][p + 1];
    }
}

// refresh the <=2 logits adjacent to the new node (after its projection GEMM)
__global__ void k_update(int it, const int* __restrict__ len,
                         const float* __restrict__ bcomp, const float* __restrict__ wq) {
    int b = blockIdx.y, q = blockIdx.x;
    int ln = len[b];
    if (ln - 2 <= it) return;
    int k = g_selpos[b];
    int p = k - 1 + q;
    if (p < 0) return;
    int np = ln - 2 - it;
    if (p >= np) return;
    float lg = pair_logit(b, g_seq[b][p], g_seq[b][p + 1], bcomp, wq);
    if (threadIdx.x == 0) g_logit[b][p] = lg;
}

__global__ void k_output(const int* __restrict__ len, float* __restrict__ out) {
    int idx = blockIdx.x * blockDim.x + threadIdx.x;
    if (idx >= B_ * D2) return;
    int b = idx >> 10;
    int d = idx & (D2 - 1);
    out[idx] = g_nodeH[14 + len[b]][b][d];
}

// ---------------- orchestration ----------------
extern "C" void kernel_launch(void* const* d_in, const int* in_sizes, int n_in,
                              void* d_out, int out_size) {
    const float* x     = (const float*)d_in[0];
    const int*   len   = (const int*)  d_in[1];
    const float* wihf  = (const float*)d_in[2];
    const float* whhf  = (const float*)d_in[3];
    const float* bf    = (const float*)d_in[4];
    const float* wihb  = (const float*)d_in[5];
    const float* whhb  = (const float*)d_in[6];
    const float* bb    = (const float*)d_in[7];
    const float* wcomp = (const float*)d_in[8];
    const float* bcomp = (const float*)d_in[9];
    const float* wq    = (const float*)d_in[10];
    float* out = (float*)d_out;

    float *p_xg, *p_nH, *p_PL, *p_PR;
    int *p_rm, *p_lal, *p_lac, *p_ial, *p_iac;
    cudaGetSymbolAddress((void**)&p_xg,   g_xg);
    cudaGetSymbolAddress((void**)&p_nH,   g_nodeH);
    cudaGetSymbolAddress((void**)&p_PL,   g_PL);
    cudaGetSymbolAddress((void**)&p_PR,   g_PR);
    cudaGetSymbolAddress((void**)&p_rm,   g_rowmap);
    cudaGetSymbolAddress((void**)&p_lal,  g_lalist);
    cudaGetSymbolAddress((void**)&p_lac,  g_lacnt);
    cudaGetSymbolAddress((void**)&p_ial,  g_italist);
    cudaGetSymbolAddress((void**)&p_iac,  g_iacnt);

    k_reset<<<1, 32>>>();
    k_init<<<(2 * B_ * H_ + 255) / 256, 256>>>(len);

    // input projections: xg_f = x @ w_ih_f^T + b_f ; xg_b = gather(x) @ w_ih_b^T + b_b
    gemm_nt<128,128,16,8,8,256><<<dim3(G4/128, (B_*L_)/128), 256>>>(
        x, H_, nullptr, nullptr, nullptr, wihf, nullptr, H_, 0, bf, nullptr, 0,
        p_xg, nullptr, G4, H_);
    gemm_nt<128,128,16,8,8,256><<<dim3(G4/128, (B_*L_)/128), 256>>>(
        x, H_, p_rm, nullptr, nullptr, wihb, nullptr, H_, 0, bb, nullptr, 0,
        p_xg + (size_t)B_ * L_ * G4, nullptr, G4, H_);

    // 16 sequential LSTM steps: fused fwd+bwd recurrent GEMM, then gates
    for (int t = 0; t < L_; t++) {
        gemm_rec<<<dim3(G4/64, B_/64, 2), 256>>>(whhf, whhb, t);
        k_gates<<<(2 * B_ * H_ + 255) / 256, 256>>>(t, len);
    }

    // leaf projections: only rows with t < len[b] (active-first permutation + early exit)
    gemm_nt<128,128,16,8,8,256><<<dim3((2*G5)/128, (16*B_)/128), 256>>>(
        p_nH, D2, nullptr, p_lal, p_lac, wcomp, wcomp + D2, 2 * D2, G5,
        nullptr, nullptr, 0, p_PL, p_PR, G5, D2);

    // initial pair logits
    k_pairinit<<<dim3(L_ - 1, B_), 256>>>(len, bcomp, wq);

    // 15 composition iterations
    for (int it = 0; it < L_ - 1; it++) {
        k_compose<<<B_, 256>>>(it, len, bcomp);
        if (it < L_ - 2) {
            gemm_nt<64,128,16,4,8,256><<<dim3((2*G5)/128, B_/64), 256>>>(
                p_nH + (size_t)(16 + it) * B_ * D2, D2, nullptr,
                p_ial + it * B_, p_iac + it,
                wcomp, wcomp + D2, 2 * D2, G5,
                nullptr, nullptr, 0,
                p_PL + (size_t)(16 + it) * B_ * G5,
                p_PR + (size_t)(16 + it) * B_ * G5, G5, D2);
            k_update<<<dim3(2, B_), 256>>>(it, len, bcomp, wq);
        }
    }

    k_output<<<(B_ * D2 + 255) / 256, 256>>>(len, out);
}